// round 9
// baseline (speedup 1.0000x reference)
#include <cuda_runtime.h>
#include <cuda_bf16.h>
#include <cstdint>

// Problem constants
#define BB 2048   // batch
#define BP 2058   // padded batch
#define TT 64     // timesteps
#define HH 64     // LSTM hidden
#define GG 256    // 4*H gates
#define NL 8      // LSTM layers
#define BT2 7     // batch rows per CTA
#define NCTA2 294 // 2058/7 -> 2 CTAs per SM

// Ping-pong inter-layer buffers, layout [T, BP, 64] (layer0 x uses cols 0-15, rest zero)
__device__ float g_bufA[(size_t)TT * BP * HH + 256];
__device__ float g_bufB[(size_t)TT * BP * HH + 256];
// Packed transposed weights: [NL][32 k4][256 j] of {pair(k0,k1), pair(k2,k3)}
// combined K = [x 0..63 | h 64..127]; layer 0 x-part beyond col 16 zeroed.
__device__ ulonglong2 g_wt[(size_t)NL * 32 * 256];

__device__ __forceinline__ float* bufptr(int s) { return s ? g_bufB : g_bufA; }

__device__ __forceinline__ float sigm(float x) {
    return __fdividef(1.0f, 1.0f + __expf(-x));
}
__device__ __forceinline__ float tanh_(float x) {
    return __fdividef(2.0f, 1.0f + __expf(-2.0f * x)) - 1.0f;
}

// ---- packed f32x2 helpers (Blackwell FFMA2; PTX-only) ----
__device__ __forceinline__ void ffma2(uint64_t& d, uint64_t a, uint64_t b) {
    asm("fma.rn.f32x2 %0, %1, %2, %0;" : "+l"(d) : "l"(a), "l"(b));
}
__device__ __forceinline__ uint64_t pack2(float lo, float hi) {
    uint64_t r;
    asm("mov.b64 %0, {%1, %2};" : "=l"(r) : "f"(lo), "f"(hi));
    return r;
}
__device__ __forceinline__ float hsum2(uint64_t v) {
    float lo, hi;
    asm("mov.b64 {%0, %1}, %2;" : "=f"(lo), "=f"(hi) : "l"(v));
    return lo + hi;
}

// ---------------------------------------------------------------------------
// Weight prep: pack all layers' combined (w_ih | w_hh) rows into g_wt, k-major
// pairs, coalesced-by-j layout. blockIdx.x = l*32 + k4; thread = gate col j.
// ---------------------------------------------------------------------------
__global__ void prep_weights(const float* __restrict__ w_ih0, const float* __restrict__ w_hh0,
                             const float* __restrict__ w_ih, const float* __restrict__ w_hh)
{
    const int l  = blockIdx.x >> 5;
    const int k4 = blockIdx.x & 31;
    const int j  = threadIdx.x;
    float w[4];
#pragma unroll
    for (int i = 0; i < 4; i++) {
        int k = k4 * 4 + i;
        float v;
        if (k < 64) {
            if (l == 0) v = (k < 16) ? w_ih0[j * 16 + k] : 0.0f;
            else        v = w_ih[((size_t)(l - 1) * GG + j) * 64 + k];
        } else {
            int kh = k - 64;
            if (l == 0) v = w_hh0[j * 64 + kh];
            else        v = w_hh[((size_t)(l - 1) * GG + j) * 64 + kh];
        }
        w[i] = v;
    }
    g_wt[(size_t)blockIdx.x * 256 + j] = make_ulonglong2(pack2(w[0], w[1]), pack2(w[2], w[3]));
}

// ---------------------------------------------------------------------------
// Input MLP: x[B,T,2] -> relu(x@w1^T+b1)@w2^T+b2 -> g_bufA[T,BP,64] (cols 0-15)
// ---------------------------------------------------------------------------
__global__ void mlp_in_kernel(const float* __restrict__ x,
                              const float* __restrict__ w1, const float* __restrict__ b1,
                              const float* __restrict__ w2, const float* __restrict__ b2)
{
    __shared__ float s_w1[16][2], s_b1[16], s_w2[16][16], s_b2[16];
    int tid = threadIdx.x;
    if (tid < 32) { s_w1[tid / 2][tid % 2] = w1[tid]; }
    if (tid < 16) { s_b1[tid] = b1[tid]; s_b2[tid] = b2[tid]; }
    if (tid >= 32 && tid < 32 + 256) {
        int i = tid - 32;
        s_w2[i / 16][i % 16] = w2[i];
    }
    __syncthreads();

    int idx = blockIdx.x * blockDim.x + tid;      // idx = b*T + t
    int b = idx / TT;
    int t = idx % TT;
    float x0 = x[(size_t)idx * 2 + 0];
    float x1 = x[(size_t)idx * 2 + 1];

    float h1[16];
#pragma unroll
    for (int j = 0; j < 16; j++) {
        float v = fmaf(s_w1[j][0], x0, fmaf(s_w1[j][1], x1, s_b1[j]));
        h1[j] = fmaxf(v, 0.0f);
    }
    float* dst = g_bufA + ((size_t)t * BP + b) * 64;
#pragma unroll
    for (int j = 0; j < 16; j++) {
        float o = s_b2[j];
#pragma unroll
        for (int k = 0; k < 16; k++) o = fmaf(s_w2[j][k], h1[k], o);
        dst[j] = o;
    }
#pragma unroll
    for (int j = 16; j < 64; j++) dst[j] = 0.0f;
}

// ---------------------------------------------------------------------------
// Fused LSTM layer, 2 CTAs/SM. 256 threads = 128 col-pairs (jA=p, jB=p+128)
// x 2 K-halves (q=0: x ks 0..63, q=1: h ks 0..63). Weights STREAMED from
// g_wt via L1D (coalesced LDG.128, ~128KB resident); accumulators for 7 rows
// live in regs (~65 total -> 2 CTAs/SM, cross-CTA overlap hides EW/barriers).
// Per step: [ML all rows] bar [EW + x(t+1) commit] bar.
// ---------------------------------------------------------------------------
__global__ void __launch_bounds__(256, 2)
lstm_fused2(int insel, int outsel, int layer,
            const float* __restrict__ b_ih, const float* __restrict__ b_hh)
{
    __shared__ __align__(16) float s_x[2][BT2 * 64];
    __shared__ __align__(16) float s_h[BT2 * 64];
    __shared__ __align__(16) float s_c[BT2 * 64];
    __shared__ __align__(16) float s_gp[8][BT2 * 64];   // plane = gate*2 + q

    const float* in  = bufptr(insel);
    float*       out = bufptr(outsel);
    const int tid = threadIdx.x;
    const int p   = tid & 127;          // column pair
    const int q   = tid >> 7;           // K half: 0 = x, 1 = h
    const int glo = p >> 6;             // gate of jA (0=i, 1=f); jB gate = 2+glo
    const int u   = p & 63;             // unit
    const int b0  = blockIdx.x * BT2;
    const ulonglong2* wtq = g_wt + ((size_t)layer * 32 + q * 16) * 256;

    uint64_t biasA = 0ull, biasB = 0ull;
    if (q == 0) {
        biasA = pack2(b_ih[p] + b_hh[p], 0.0f);
        biasB = pack2(b_ih[p + 128] + b_hh[p + 128], 0.0f);
    }

    // h0 = c0 = 0; stage x(0)
    for (int i = tid; i < BT2 * 64; i += 256) { s_h[i] = 0.0f; s_c[i] = 0.0f; }
    if (tid < BT2 * 16)
        ((float4*)s_x[0])[tid] = ((const float4*)(in + (size_t)b0 * 64))[tid];
    __syncthreads();

    for (int t = 0; t < TT; t++) {
        const int cur = t & 1;

        // prefetch x(t+1) into regs (hidden under mainloop)
        float4 pf;
        const bool do_pf = (t + 1 < TT) && (tid < BT2 * 16);
        if (do_pf)
            pf = ((const float4*)(in + ((size_t)(t + 1) * BP + b0) * 64))[tid];

        const float* ap = q ? s_h : s_x[cur];

        // ---- mainloop: all 7 rows, K window of 64 ks in 16 chunks of 4 ----
        uint64_t accA[BT2], accB[BT2];
#pragma unroll
        for (int r = 0; r < BT2; r++) { accA[r] = biasA; accB[r] = biasB; }

#pragma unroll
        for (int k4 = 0; k4 < 16; k4++) {
            ulonglong2 wA = wtq[(size_t)k4 * 256 + p];        // LDG.128, L1-resident
            ulonglong2 wB = wtq[(size_t)k4 * 256 + p + 128];
#pragma unroll
            for (int r = 0; r < BT2; r++) {
                ulonglong2 v = *(const ulonglong2*)(ap + r * 64 + k4 * 4);  // LDS.128 bcast
                ffma2(accA[r], v.x, wA.x);
                ffma2(accA[r], v.y, wA.y);
                ffma2(accB[r], v.x, wB.x);
                ffma2(accB[r], v.y, wB.y);
            }
        }
#pragma unroll
        for (int r = 0; r < BT2; r++) {
            s_gp[glo * 2 + q][r * 64 + u]       = hsum2(accA[r]);
            s_gp[(2 + glo) * 2 + q][r * 64 + u] = hsum2(accB[r]);
        }
        __syncthreads();  // partials ready

        // ---- elementwise: 448 units over 256 threads ----
#pragma unroll
        for (int e = 0; e < 2; e++) {
            int ul = e * 256 + tid;
            if (ul < BT2 * 64) {
                int r  = ul >> 6;
                int uu = ul & 63;
                float gi = s_gp[0][r * 64 + uu] + s_gp[1][r * 64 + uu];
                float gf = s_gp[2][r * 64 + uu] + s_gp[3][r * 64 + uu];
                float gg = s_gp[4][r * 64 + uu] + s_gp[5][r * 64 + uu];
                float go = s_gp[6][r * 64 + uu] + s_gp[7][r * 64 + uu];
                float iv = sigm(gi), fv = sigm(gf), gv = tanh_(gg), ov = sigm(go);
                float cc = fmaf(fv, s_c[r * 64 + uu], iv * gv);
                float hh = ov * tanh_(cc);
                s_c[r * 64 + uu] = cc;
                s_h[r * 64 + uu] = hh;
                out[((size_t)t * BP + b0 + r) * 64 + uu] = hh;
            }
        }
        // commit x(t+1) into the other buffer
        if (do_pf)
            ((float4*)s_x[cur ^ 1])[tid] = pf;
        __syncthreads();  // h final, x(t+1) staged
    }
}

// ---------------------------------------------------------------------------
// Output MLP: h[T,BP,64] -> relu(h@wo1^T+bo1)@wo2^T+bo2 -> out[B,T,4]
// ---------------------------------------------------------------------------
__global__ void mlp_out_kernel(int insel,
                               const float* __restrict__ wo1, const float* __restrict__ bo1,
                               const float* __restrict__ wo2, const float* __restrict__ bo2,
                               float* __restrict__ outp)
{
    __shared__ float s_w1[32][64];
    __shared__ float s_b1[32];
    __shared__ float s_w2[4][32];
    __shared__ float s_b2[4];
    int tid = threadIdx.x;
    for (int i = tid; i < 32 * 64; i += 256) s_w1[i / 64][i % 64] = wo1[i];
    if (tid < 32) s_b1[tid] = bo1[tid];
    if (tid < 128) s_w2[tid / 32][tid % 32] = wo2[tid];
    if (tid < 4) s_b2[tid] = bo2[tid];
    __syncthreads();

    const float* in = bufptr(insel);
    int idx = blockIdx.x * blockDim.x + tid;   // idx = t*B + b (coalesced h reads)
    int t = idx / BB;
    int b = idx % BB;

    float h[64];
    const float4* src = reinterpret_cast<const float4*>(in + ((size_t)t * BP + b) * 64);
#pragma unroll
    for (int i = 0; i < 16; i++) {
        float4 v = src[i];
        h[4 * i + 0] = v.x; h[4 * i + 1] = v.y; h[4 * i + 2] = v.z; h[4 * i + 3] = v.w;
    }

    float h2[32];
#pragma unroll
    for (int j = 0; j < 32; j++) {
        float o = s_b1[j];
#pragma unroll
        for (int k = 0; k < 64; k++) o = fmaf(s_w1[j][k], h[k], o);
        h2[j] = fmaxf(o, 0.0f);
    }
    float* dst = outp + ((size_t)b * TT + t) * 4;
#pragma unroll
    for (int j = 0; j < 4; j++) {
        float o = s_b2[j];
#pragma unroll
        for (int k = 0; k < 32; k++) o = fmaf(s_w2[j][k], h2[k], o);
        dst[j] = o;
    }
}

// ---------------------------------------------------------------------------
extern "C" void kernel_launch(void* const* d_in, const int* in_sizes, int n_in,
                              void* d_out, int out_size)
{
    const float* x     = (const float*)d_in[0];
    const float* w1    = (const float*)d_in[1];
    const float* b1    = (const float*)d_in[2];
    const float* w2    = (const float*)d_in[3];
    const float* b2    = (const float*)d_in[4];
    const float* w_ih0 = (const float*)d_in[5];
    const float* w_hh0 = (const float*)d_in[6];
    const float* b_ih0 = (const float*)d_in[7];
    const float* b_hh0 = (const float*)d_in[8];
    const float* w_ih  = (const float*)d_in[9];   // (7, 256, 64)
    const float* w_hh  = (const float*)d_in[10];  // (7, 256, 64)
    const float* b_ih  = (const float*)d_in[11];  // (7, 256)
    const float* b_hh  = (const float*)d_in[12];  // (7, 256)
    const float* wo1   = (const float*)d_in[13];
    const float* bo1   = (const float*)d_in[14];
    const float* wo2   = (const float*)d_in[15];
    const float* bo2   = (const float*)d_in[16];
    float* outp = (float*)d_out;

    const int nelem = BB * TT;               // 131072

    prep_weights<<<NL * 32, 256>>>(w_ih0, w_hh0, w_ih, w_hh);
    mlp_in_kernel<<<nelem / 256, 256>>>(x, w1, b1, w2, b2);

    int cur = 0;
    for (int l = 0; l < NL; l++) {
        int nxt = cur ^ 1;
        const float* bi = (l == 0) ? b_ih0 : b_ih + (size_t)(l - 1) * GG;
        const float* bh = (l == 0) ? b_hh0 : b_hh + (size_t)(l - 1) * GG;
        lstm_fused2<<<NCTA2, 256>>>(cur, nxt, l, bi, bh);
        cur = nxt;
    }

    mlp_out_kernel<<<nelem / 256, 256>>>(cur, wo1, bo1, wo2, bo2, outp);
}